// round 11
// baseline (speedup 1.0000x reference)
#include <cuda_runtime.h>
#include <math.h>

#define NQ 16
#define NS 65536
#define BATCH 256
#define SLIM (BATCH * NS)
#define MLIM (BATCH * 3 * NQ * 4)

__device__ __align__(16) float g_state[SLIM];
__device__ __align__(16) float g_M[MLIM];
__device__ float g_P[48];
__device__ __align__(16) float g_F[BATCH * 2048];
__device__ __align__(16) float g_H[BATCH * 64];

__device__ __forceinline__ float sigm(float x) { return 1.0f / (1.0f + expf(-x)); }

template <int N>
__device__ __forceinline__ void gate_reg(float* v, int kb,
                                         float m00, float m01, float m10, float m11) {
    #pragma unroll
    for (int i = 0; i < N; i++) if (!(i & kb)) {
        const int j = i | kb;
        float a = v[i], c = v[j];
        v[i] = m00 * a + m01 * c;
        v[j] = m10 * a + m11 * c;
    }
}
template <int N>
__device__ __forceinline__ void cnot_reg(float* v, int cb, int tb, float p) {
    const float om = 1.f - p;
    #pragma unroll
    for (int i = 0; i < N; i++) if ((i & cb) && !(i & tb)) {
        const int j = i | tb;
        float a = v[i], c = v[j];
        v[i] = om * a + p * c;
        v[j] = om * c + p * a;
    }
}
template <int N>
__device__ __forceinline__ void cnot_reg_ext(float* v, int tb, bool ctrl, float p) {
    const float pp = ctrl ? p : 0.f;
    const float oo = ctrl ? 1.f - p : 1.f;
    #pragma unroll
    for (int i = 0; i < N; i++) if (!(i & tb)) {
        const int j = i | tb;
        float a = v[i], c = v[j];
        v[i] = oo * a + pp * c;
        v[j] = oo * c + pp * a;
    }
}

// 4-wide variants: w[64] = 16 high-states x 4 consecutive low indices.
__device__ __forceinline__ void gate4(float* w, int kb,
                                      float m00, float m01, float m10, float m11) {
    #pragma unroll
    for (int i = 0; i < 16; i++) if (!(i & kb)) {
        const int j = i | kb;
        #pragma unroll
        for (int c = 0; c < 4; c++) {
            float a = w[i * 4 + c], d = w[j * 4 + c];
            w[i * 4 + c] = m00 * a + m01 * d;
            w[j * 4 + c] = m10 * a + m11 * d;
        }
    }
}
__device__ __forceinline__ void cnot4(float* w, int cb, int tb, float p) {
    const float om = 1.f - p;
    #pragma unroll
    for (int i = 0; i < 16; i++) if ((i & cb) && !(i & tb)) {
        const int j = i | tb;
        #pragma unroll
        for (int c = 0; c < 4; c++) {
            float a = w[i * 4 + c], d = w[j * 4 + c];
            w[i * 4 + c] = om * a + p * d;
            w[j * 4 + c] = om * d + p * a;
        }
    }
}
__device__ __forceinline__ void cnot4_ext(float* w, int tb, bool ctrl, float p) {
    const float pp = ctrl ? p : 0.f;
    const float oo = ctrl ? 1.f - p : 1.f;
    #pragma unroll
    for (int i = 0; i < 16; i++) if (!(i & tb)) {
        const int j = i | tb;
        #pragma unroll
        for (int c = 0; c < 4; c++) {
            float a = w[i * 4 + c], d = w[j * 4 + c];
            w[i * 4 + c] = oo * a + pp * d;
            w[j * 4 + c] = oo * d + pp * a;
        }
    }
}

__global__ void dummy_kernel(float* outf, unsigned capF) {
    if (capF > 0) outf[0] = 0.f;
}

// ---------------------------------------------------------------------------
__global__ void mlp_kernel(const float* __restrict__ X,
                           const float* __restrict__ rot,
                           const float* __restrict__ ent,
                           const float* __restrict__ W1,
                           const float* __restrict__ b1,
                           const float* __restrict__ W2,
                           const float* __restrict__ b2)
{
    __shared__ float sx[100];
    __shared__ float sa[64];
    __shared__ float sh[16];
    const int b = blockIdx.x;
    const int j = threadIdx.x;

    if (b == 0 && j < 45) g_P[j] = sigm(ent[j]);

    for (int k = j; k < 100; k += 64) sx[k] = X[b * 100 + k];
    __syncthreads();
    {
        float s = b1[j];
        #pragma unroll 4
        for (int k = 0; k < 100; k++) s = fmaf(sx[k], W1[k * 64 + j], s);
        sa[j] = s > 0.f ? s : 0.f;
    }
    __syncthreads();
    if (j < 16) {
        float s = b2[j];
        #pragma unroll 8
        for (int k = 0; k < 64; k++) s = fmaf(sa[k], W2[k * 16 + j], s);
        sh[j] = tanhf(s);
    }
    __syncthreads();
    if (j < 48) {
        const int l = j >> 4, q = j & 15;
        float hv = 0.5f * sh[q];
        float ax = rot[(l * 16 + q) * 3 + 0] * hv;
        float ay = rot[(l * 16 + q) * 3 + 1] * hv;
        float az = rot[(l * 16 + q) * 3 + 2] * hv;
        float cx, sx2, cy, sy, cz, sz;
        sincosf(ax, &sx2, &cx);
        sincosf(ay, &sy,  &cy);
        sincosf(az, &sz,  &cz);
        float* m = &g_M[((b * 3 + l) * NQ + q) * 4];
        m[0] =  cx * cy * cz;
        m[1] = -sx2 * sy * sz;
        m[2] =  sx2 * sy * cz;
        m[3] =  cx * cy * sz;
    }
}

// ---------------------------------------------------------------------------
// Layer-0 closed form (see R10): F' (2048) and H_0,H_1 (32 each) per batch.
// ---------------------------------------------------------------------------
__global__ void __launch_bounds__(256) prep_kernel()
{
    __shared__ float fA[2048], fB[2048];
    __shared__ float gg[2][32];
    const int b = blockIdx.x;
    const unsigned t = threadIdx.x;
    const float* M = &g_M[b * 3 * 64];

    float ph = 1.f;
    #pragma unroll
    for (int q = 3; q < 11; q++) ph *= M[q * 4 + (((t >> (q - 3)) & 1) ? 2 : 0)];
    #pragma unroll
    for (int r = 0; r < 8; r++) {
        float pr = ph;
        pr *= M[0 + ((r & 1) ? 2 : 0)];
        pr *= M[4 + ((r & 2) ? 2 : 0)];
        pr *= M[8 + ((r & 4) ? 2 : 0)];
        fA[t * 8 + r] = pr;
    }
    __syncthreads();

    float* cur = fA;
    float* nxt = fB;
    #pragma unroll
    for (int i = 0; i < 10; i++) {
        const float p = g_P[i], om = 1.f - p;
        const unsigned cb = 1u << i, tb = 1u << (i + 1);
        #pragma unroll
        for (int k = 0; k < 8; k++) {
            const unsigned l = t + 256u * k;
            const float a = cur[l];
            nxt[l] = (l & cb) ? (om * a + p * cur[l ^ tb]) : a;
        }
        __syncthreads();
        float* tmp = cur; cur = nxt; nxt = tmp;
    }
    #pragma unroll
    for (int k = 0; k < 8; k++) {
        const unsigned l = t + 256u * k;
        g_F[b * 2048 + l] = cur[l];
    }

    if (t < 32) {
        float g = 1.f;
        #pragma unroll
        for (int q = 11; q < 16; q++) g *= M[q * 4 + (((t >> (q - 11)) & 1) ? 2 : 0)];
        gg[0][t] = g;
    }
    __syncthreads();
    if (t < 32) {
        const float p = g_P[10];
        gg[1][t] = (1.f - p) * gg[0][t] + p * gg[0][t ^ 1u];
    }
    __syncthreads();
    #pragma unroll
    for (int i = 11; i < 15; i++) {
        const float p = g_P[i], om = 1.f - p;
        const unsigned cb = 1u << (i - 11), tb = 1u << (i - 10);
        float r = 0.f;
        if (t < 64) {
            const unsigned vv = t >> 5, h = t & 31u;
            const float a = gg[vv][h];
            r = (h & cb) ? (om * a + p * gg[vv][h ^ tb]) : a;
        }
        __syncthreads();
        if (t < 64) gg[t >> 5][t & 31u] = r;
        __syncthreads();
    }
    if (t < 64) g_H[b * 64 + t] = gg[t >> 5][t & 31u];
}

// ---------------------------------------------------------------------------
// Pass A (unchanged from R10): slab bits 0..11, 2 padded-smem transposes.
// ---------------------------------------------------------------------------
#define SMEM_FLOATS 5376
template <int LAYER, int MODE>
__global__ void __launch_bounds__(256) passA_kernel()
{
    __shared__ float sm[SMEM_FLOATS];
    const int hi = blockIdx.x & 15;
    const int b  = blockIdx.x >> 4;
    const unsigned t = threadIdx.x;
    const float* M = &g_M[(b * 3 + LAYER) * 64];
    const float* P = &g_P[LAYER * 15];
    const unsigned base = ((unsigned)b << 16) + ((unsigned)hi << 12);

    float v[16];
    if (MODE == 1) {
        const float hval = g_H[(unsigned)b * 64u + ((t >> 6) & 1u) * 32u
                               + (((unsigned)hi << 1) | ((t >> 7) & 1u))];
        const float* Fp = &g_F[(unsigned)b * 2048u + ((t & 127u) << 4)];
        #pragma unroll
        for (int k = 0; k < 4; k++) {
            const float4 u = *(const float4*)&Fp[4 * k];
            v[4*k+0] = u.x * hval; v[4*k+1] = u.y * hval;
            v[4*k+2] = u.z * hval; v[4*k+3] = u.w * hval;
        }
    } else {
        #pragma unroll
        for (int k = 0; k < 4; k++) {
            const float4 u = *(const float4*)&g_state[base + (t << 4) + 4u * k];
            v[4*k+0] = u.x; v[4*k+1] = u.y; v[4*k+2] = u.z; v[4*k+3] = u.w;
        }
    }
    gate_reg<16>(v, 1, M[0],  M[1],  M[2],  M[3]);
    gate_reg<16>(v, 2, M[4],  M[5],  M[6],  M[7]);
    gate_reg<16>(v, 4, M[8],  M[9],  M[10], M[11]);
    gate_reg<16>(v, 8, M[12], M[13], M[14], M[15]);
    cnot_reg<16>(v, 1, 2, P[0]);
    cnot_reg<16>(v, 2, 4, P[1]);
    cnot_reg<16>(v, 4, 8, P[2]);

    {
        float4* s4 = (float4*)sm;
        const unsigned w4 = t * 5u + 4u * (t >> 4);
        #pragma unroll
        for (int k = 0; k < 4; k++)
            s4[w4 + k] = make_float4(v[4*k], v[4*k+1], v[4*k+2], v[4*k+3]);
    }
    __syncthreads();
    {
        const unsigned rbase = (t & 15u) + 336u * (t >> 4);
        #pragma unroll
        for (int r = 0; r < 16; r++) v[r] = sm[rbase + 20u * r];
    }
    gate_reg<16>(v, 1, M[16], M[17], M[18], M[19]);
    gate_reg<16>(v, 2, M[20], M[21], M[22], M[23]);
    gate_reg<16>(v, 4, M[24], M[25], M[26], M[27]);
    gate_reg<16>(v, 8, M[28], M[29], M[30], M[31]);
    cnot_reg_ext<16>(v, 1, (t & 8u) != 0, P[3]);
    cnot_reg<16>(v, 1, 2, P[4]);
    cnot_reg<16>(v, 2, 4, P[5]);
    cnot_reg<16>(v, 4, 8, P[6]);

    __syncthreads();

    {
        const unsigned wbase = (t & 15u) + 272u * (t >> 4);
        #pragma unroll
        for (int r = 0; r < 16; r++) sm[wbase + 16u * r] = v[r];
    }
    __syncthreads();
    {
        #pragma unroll
        for (int r = 0; r < 16; r++) v[r] = sm[272u * r + t];
    }
    gate_reg<16>(v, 1, M[32], M[33], M[34], M[35]);
    gate_reg<16>(v, 2, M[36], M[37], M[38], M[39]);
    gate_reg<16>(v, 4, M[40], M[41], M[42], M[43]);
    gate_reg<16>(v, 8, M[44], M[45], M[46], M[47]);
    cnot_reg_ext<16>(v, 1, (t & 128u) != 0, P[7]);
    cnot_reg<16>(v, 1, 2, P[8]);
    cnot_reg<16>(v, 2, 4, P[9]);
    cnot_reg<16>(v, 4, 8, P[10]);

    #pragma unroll
    for (int r = 0; r < 16; r++) g_state[base + ((unsigned)r << 8) + t] = v[r];
}

// ---------------------------------------------------------------------------
// Pass B, 4-wide: each thread owns 4 consecutive low indices x 16 high states
// (bits 12..15), i.e. 64 floats, all global I/O via float4.
// Grid: blockIdx.x = b*4 + blk, blk = low bits 10..11; thread low = blk<<10|t<<2.
// C11 ctrl = low bit 11 — uniform across a thread's 4 lows (they differ in
// bits 0..1 only).
// ---------------------------------------------------------------------------
template <int LAYER, bool OUT>
__global__ void __launch_bounds__(256, 2) passB_kernel(float* __restrict__ outf,
                                                       unsigned capF, int mode)
{
    const int blk = blockIdx.x & 3;
    const int b = blockIdx.x >> 2;
    const unsigned t = threadIdx.x;
    const unsigned low = ((unsigned)blk << 10) | (t << 2);
    const float* M = &g_M[(b * 3 + LAYER) * 64];
    const float* P = &g_P[LAYER * 15];
    const unsigned base = ((unsigned)b << 16) + low;

    float w[64];
    #pragma unroll
    for (int k = 0; k < 16; k++) {
        const float4 u = *(const float4*)&g_state[base + ((unsigned)k << 12)];
        w[k*4+0] = u.x; w[k*4+1] = u.y; w[k*4+2] = u.z; w[k*4+3] = u.w;
    }

    gate4(w, 1, M[48], M[49], M[50], M[51]);  // G12
    gate4(w, 2, M[52], M[53], M[54], M[55]);  // G13
    gate4(w, 4, M[56], M[57], M[58], M[59]);  // G14
    gate4(w, 8, M[60], M[61], M[62], M[63]);  // G15
    cnot4_ext(w, 1, (low & 2048u) != 0, P[11]);  // C11
    cnot4(w, 1, 2, P[12]);                       // C12
    cnot4(w, 2, 4, P[13]);                       // C13
    cnot4(w, 4, 8, P[14]);                       // C14

    if (OUT) {
        if (mode == 1) {
            #pragma unroll
            for (int k = 0; k < 16; k++) {
                const unsigned idx = base + ((unsigned)k << 12);
                const unsigned p2 = 2u * idx;   // float4-aligned (idx % 4 == 0)
                if (p2 + 7u < capF) {
                    *(float4*)&outf[p2]     = make_float4(w[k*4+0], 0.f, w[k*4+1], 0.f);
                    *(float4*)&outf[p2 + 4] = make_float4(w[k*4+2], 0.f, w[k*4+3], 0.f);
                }
            }
        } else {
            #pragma unroll
            for (int k = 0; k < 16; k++) {
                const unsigned idx = base + ((unsigned)k << 12);
                if (idx + 3u < capF)
                    *(float4*)&outf[idx] = make_float4(w[k*4+0], w[k*4+1], w[k*4+2], w[k*4+3]);
            }
        }
    } else {
        #pragma unroll
        for (int k = 0; k < 16; k++)
            *(float4*)&g_state[base + ((unsigned)k << 12)] =
                make_float4(w[k*4+0], w[k*4+1], w[k*4+2], w[k*4+3]);
    }
}

// ---------------------------------------------------------------------------
extern "C" void kernel_launch(void* const* d_in, const int* in_sizes, int n_in,
                              void* d_out, int out_size)
{
    static const long long want[7] = {25600, 144, 45, 6400, 64, 1024, 16};
    const float* ptr[7] = {0, 0, 0, 0, 0, 0, 0};

    bool bound = false;
    for (int scale = 1; scale <= 4 && !bound; scale *= 4) {
        const float* tmp[7] = {0, 0, 0, 0, 0, 0, 0};
        int m = 0;
        for (int i = 0; i < n_in; i++) {
            long long s = (long long)in_sizes[i];
            for (int j = 0; j < 7; j++) {
                if (!tmp[j] && s == want[j] * scale) { tmp[j] = (const float*)d_in[i]; m++; break; }
            }
        }
        if (m == 7) { for (int j = 0; j < 7; j++) ptr[j] = tmp[j]; bound = true; }
    }
    if (!bound && n_in >= 7) {
        for (int j = 0; j < 7; j++) ptr[j] = (const float*)d_in[j];
        bound = true;
    }

    float* outf = (float*)d_out;

    long long os = (long long)out_size;
    unsigned capF;
    int mode;
    if (os >= 33554432LL)      { mode = 1; capF = 33554432u; }
    else if (os == 16777216LL) { mode = 0; capF = 16777216u; }
    else {
        mode = 0;
        long long c = os > 0 ? os : 0;
        if (c > 33554432LL) c = 33554432LL;
        capF = (unsigned)c;
    }

    if (!bound || !outf) {
        dummy_kernel<<<1, 32>>>(outf, capF);
        return;
    }

    mlp_kernel<<<BATCH, 64>>>(ptr[0], ptr[1], ptr[2], ptr[3], ptr[4], ptr[5], ptr[6]);
    prep_kernel<<<BATCH, 256>>>();

    const int GA = 16 * BATCH;  // 4096 blocks
    const int GB = 4 * BATCH;   // 1024 blocks (4-wide pass B)
    passA_kernel<1, 1><<<GA, 256>>>();
    passB_kernel<1, false><<<GB, 256>>>(outf, capF, mode);
    passA_kernel<2, 0><<<GA, 256>>>();
    passB_kernel<2, true ><<<GB, 256>>>(outf, capF, mode);
}